// round 7
// baseline (speedup 1.0000x reference)
#include <cuda_runtime.h>
#include <cuda_bf16.h>

#define IMG_H 512
#define IMG_W 512
#define N_IMG 256
#define WCHUNK 32                 // rows per warp
#define WARPS  4                  // warps per CTA
#define ROWS_PER_CTA (WCHUNK * WARPS)
#define W4 (IMG_W / 4)            // 128 float4 per row

__device__ __forceinline__ int mirror_idx(int idx, int n) {
    const int p = 2 * (n - 1);
    int i = abs(idx) % p;
    return (i >= n) ? (p - i) : i;
}

// Warp-autonomous: each warp owns a 32-row strip + private smem row buffer.
// grid = 1024 CTAs -> single resident wave on 148 SMs (no partial wave).
// Per row: 4 prefetched LDG.128/thread (MLP=4), vertical blend in regs,
// STS, __syncwarp, horizontal pass via conflict-free LDS.128, streaming STG.
// Row reuse: rA(y) == rB(y-1) exactly -> 1 global row read per output row.
__global__ __launch_bounds__(128, 8)
void shift_bilinear_kernel(const float* __restrict__ images,
                           const float* __restrict__ dxdy,
                           float* __restrict__ out) {
    __shared__ float4 sb[WARPS][2][W4];

    const int t = threadIdx.x & 31;
    const int w = threadIdx.x >> 5;
    const int b = blockIdx.y;
    const int y0 = blockIdx.x * ROWS_PER_CTA + w * WCHUNK;

    const float dy = __ldg(&dxdy[2 * b + 0]);
    const float dx = __ldg(&dxdy[2 * b + 1]);

    // per-image constants: floor(y - dy) = y + floor(-dy)
    const float syf = floorf(-dy);
    const float sxf = floorf(-dx);
    const float fy  = (-dy) - syf;
    const float fx  = (-dx) - sxf;
    const float wy0 = 1.0f - fy;
    const float wx0 = 1.0f - fx;
    const int   sy  = (int)syf;
    const int   sx  = (int)sxf;
    const int   kk  = sx >> 2;     // uniform float4-index shift
    const int   sel = sx & 3;      // uniform sub-word select

    const float4* imgv = (const float4*)(images + (size_t)b * IMG_H * IMG_W);
    float4*       outv = (float4*)(out + (size_t)b * IMG_H * IMG_W);

    // preload rA (src row for y0) and rB (next), lane t holds chunks c*32+t
    float4 rA[4], rB[4], rC[4];
    {
        const size_t ra = (size_t)mirror_idx(y0 + sy,     IMG_H) * W4;
        const size_t rb = (size_t)mirror_idx(y0 + sy + 1, IMG_H) * W4;
#pragma unroll
        for (int c = 0; c < 4; c++) rA[c] = imgv[ra + c * 32 + t];
#pragma unroll
        for (int c = 0; c < 4; c++) rB[c] = imgv[rb + c * 32 + t];
    }

    for (int i = 0; i < WCHUNK; ++i) {
        const int y = y0 + i;

        // prefetch next source row (consumed next iteration) — 4 back-to-back LDG.128
        if (i + 1 < WCHUNK) {
            const size_t rc = (size_t)mirror_idx(y + sy + 2, IMG_H) * W4;
#pragma unroll
            for (int c = 0; c < 4; c++) rC[c] = imgv[rc + c * 32 + t];
        }

        // vertical blend -> private smem buffer (double buffered)
        float4* S = sb[w][i & 1];
#pragma unroll
        for (int c = 0; c < 4; c++) {
            float4 br;
            br.x = wy0 * rA[c].x + fy * rB[c].x;
            br.y = wy0 * rA[c].y + fy * rB[c].y;
            br.z = wy0 * rA[c].z + fy * rB[c].z;
            br.w = wy0 * rA[c].w + fy * rB[c].w;
            S[c * 32 + t] = br;
        }
        __syncwarp();   // STS -> LDS visibility within the warp

        // horizontal pass: output float4 j = c*32+t needs blended float4s j+kk, j+kk+1
        float4* orow = outv + (size_t)y * W4;
#pragma unroll
        for (int c = 0; c < 4; c++) {
            const int j  = c * 32 + t;
            const int q0 = j + kk;
            float4 res;
            if (q0 >= 0 && q0 <= (W4 - 2)) {
                const float4 A = S[q0];
                const float4 B = S[q0 + 1];
                float b0, b1, b2, b3, b4;
                switch (sel) {  // uniform across warp
                    case 0:  b0 = A.x; b1 = A.y; b2 = A.z; b3 = A.w; b4 = B.x; break;
                    case 1:  b0 = A.y; b1 = A.z; b2 = A.w; b3 = B.x; b4 = B.y; break;
                    case 2:  b0 = A.z; b1 = A.w; b2 = B.x; b3 = B.y; b4 = B.z; break;
                    default: b0 = A.w; b1 = B.x; b2 = B.y; b3 = B.z; b4 = B.w; break;
                }
                res.x = wx0 * b0 + fx * b1;
                res.y = wx0 * b1 + fx * b2;
                res.z = wx0 * b2 + fx * b3;
                res.w = wx0 * b3 + fx * b4;
            } else {
                const float* sf = (const float*)S;
                float r[4];
#pragma unroll
                for (int jj = 0; jj < 4; jj++) {
                    const int x0  = 4 * j + sx + jj;
                    const int xm0 = mirror_idx(x0,     IMG_W);
                    const int xm1 = mirror_idx(x0 + 1, IMG_W);
                    r[jj] = wx0 * sf[xm0] + fx * sf[xm1];
                }
                res.x = r[0]; res.y = r[1]; res.z = r[2]; res.w = r[3];
            }
            __stcs(&orow[j], res);   // streaming store: output is never re-read
        }

#pragma unroll
        for (int c = 0; c < 4; c++) { rA[c] = rB[c]; rB[c] = rC[c]; }
    }
}

extern "C" void kernel_launch(void* const* d_in, const int* in_sizes, int n_in,
                              void* d_out, int out_size) {
    const float* images = (const float*)d_in[0];  // (256, 512, 512, 1) f32
    const float* dxdy   = (const float*)d_in[1];  // (256, 2) f32
    float* out = (float*)d_out;                   // (256, 512, 512) f32

    dim3 grid(IMG_H / ROWS_PER_CTA, N_IMG);       // (4, 256) = 1024 CTAs -> single wave
    dim3 block(WARPS * 32);
    shift_bilinear_kernel<<<grid, block>>>(images, dxdy, out);
}

// round 8
// speedup vs baseline: 1.0032x; 1.0032x over previous
#include <cuda_runtime.h>
#include <cuda_bf16.h>

#define IMG_H 512
#define IMG_W 512
#define N_IMG 256
#define WCHUNK 16                 // rows per warp
#define WARPS  4                  // warps per CTA
#define ROWS_PER_CTA (WCHUNK * WARPS)
#define W4 (IMG_W / 4)            // 128 float4 per row

__device__ __forceinline__ int mirror_idx(int idx, int n) {
    const int p = 2 * (n - 1);
    int i = abs(idx) % p;
    return (i >= n) ? (p - i) : i;
}

// Warp-autonomous: each warp owns a 16-row strip + private smem row buffer.
// grid = 2048 CTAs (proven best: max resident warps in wave 1, work-steal
// backfill in wave 2). Per row: 4 prefetched LDG.128/thread (MLP=4),
// vertical blend in regs, STS, __syncwarp, horizontal pass via conflict-free
// LDS.128, streaming STG (__stcs; output never re-read).
// Row reuse: rA(y) == rB(y-1) exactly -> 1 global row read per output row.
__global__ __launch_bounds__(128, 8)
void shift_bilinear_kernel(const float* __restrict__ images,
                           const float* __restrict__ dxdy,
                           float* __restrict__ out) {
    __shared__ float4 sb[WARPS][2][W4];

    const int t = threadIdx.x & 31;
    const int w = threadIdx.x >> 5;
    const int b = blockIdx.y;
    const int y0 = blockIdx.x * ROWS_PER_CTA + w * WCHUNK;

    const float dy = __ldg(&dxdy[2 * b + 0]);
    const float dx = __ldg(&dxdy[2 * b + 1]);

    // per-image constants: floor(y - dy) = y + floor(-dy)
    const float syf = floorf(-dy);
    const float sxf = floorf(-dx);
    const float fy  = (-dy) - syf;
    const float fx  = (-dx) - sxf;
    const float wy0 = 1.0f - fy;
    const float wx0 = 1.0f - fx;
    const int   sy  = (int)syf;
    const int   sx  = (int)sxf;
    const int   kk  = sx >> 2;     // uniform float4-index shift
    const int   sel = sx & 3;      // uniform sub-word select

    const float4* imgv = (const float4*)(images + (size_t)b * IMG_H * IMG_W);
    float4*       outv = (float4*)(out + (size_t)b * IMG_H * IMG_W);

    // preload rA (src row for y0) and rB (next), lane t holds chunks c*32+t
    float4 rA[4], rB[4], rC[4];
    {
        const float4* ra = imgv + (size_t)mirror_idx(y0 + sy,     IMG_H) * W4;
        const float4* rb = imgv + (size_t)mirror_idx(y0 + sy + 1, IMG_H) * W4;
#pragma unroll
        for (int c = 0; c < 4; c++) rA[c] = ra[c * 32 + t];
#pragma unroll
        for (int c = 0; c < 4; c++) rB[c] = rb[c * 32 + t];
    }

    for (int i = 0; i < WCHUNK; ++i) {
        const int y = y0 + i;

        // prefetch next source row (consumed next iteration) — 4 back-to-back LDG.128
        if (i + 1 < WCHUNK) {
            const float4* rc = imgv + (size_t)mirror_idx(y + sy + 2, IMG_H) * W4;
#pragma unroll
            for (int c = 0; c < 4; c++) rC[c] = rc[c * 32 + t];
        }

        // vertical blend -> private smem buffer (double buffered)
        float4* S = sb[w][i & 1];
#pragma unroll
        for (int c = 0; c < 4; c++) {
            float4 br;
            br.x = wy0 * rA[c].x + fy * rB[c].x;
            br.y = wy0 * rA[c].y + fy * rB[c].y;
            br.z = wy0 * rA[c].z + fy * rB[c].z;
            br.w = wy0 * rA[c].w + fy * rB[c].w;
            S[c * 32 + t] = br;
        }
        __syncwarp();   // STS -> LDS visibility within the warp

        // horizontal pass: output float4 j = c*32+t needs blended float4s j+kk, j+kk+1
        float4* orow = outv + (size_t)y * W4;
#pragma unroll
        for (int c = 0; c < 4; c++) {
            const int j  = c * 32 + t;
            const int q0 = j + kk;
            float4 res;
            if (q0 >= 0 && q0 <= (W4 - 2)) {
                const float4 A = S[q0];
                const float4 B = S[q0 + 1];
                float b0, b1, b2, b3, b4;
                switch (sel) {  // uniform across warp
                    case 0:  b0 = A.x; b1 = A.y; b2 = A.z; b3 = A.w; b4 = B.x; break;
                    case 1:  b0 = A.y; b1 = A.z; b2 = A.w; b3 = B.x; b4 = B.y; break;
                    case 2:  b0 = A.z; b1 = A.w; b2 = B.x; b3 = B.y; b4 = B.z; break;
                    default: b0 = A.w; b1 = B.x; b2 = B.y; b3 = B.z; b4 = B.w; break;
                }
                res.x = wx0 * b0 + fx * b1;
                res.y = wx0 * b1 + fx * b2;
                res.z = wx0 * b2 + fx * b3;
                res.w = wx0 * b3 + fx * b4;
            } else {
                const float* sf = (const float*)S;
                float r[4];
#pragma unroll
                for (int jj = 0; jj < 4; jj++) {
                    const int x0  = 4 * j + sx + jj;
                    const int xm0 = mirror_idx(x0,     IMG_W);
                    const int xm1 = mirror_idx(x0 + 1, IMG_W);
                    r[jj] = wx0 * sf[xm0] + fx * sf[xm1];
                }
                res.x = r[0]; res.y = r[1]; res.z = r[2]; res.w = r[3];
            }
            __stcs(&orow[j], res);   // streaming store: output is never re-read
        }

#pragma unroll
        for (int c = 0; c < 4; c++) { rA[c] = rB[c]; rB[c] = rC[c]; }
    }
}

extern "C" void kernel_launch(void* const* d_in, const int* in_sizes, int n_in,
                              void* d_out, int out_size) {
    const float* images = (const float*)d_in[0];  // (256, 512, 512, 1) f32
    const float* dxdy   = (const float*)d_in[1];  // (256, 2) f32
    float* out = (float*)d_out;                   // (256, 512, 512) f32

    dim3 grid(IMG_H / ROWS_PER_CTA, N_IMG);       // (8, 256) = 2048 CTAs
    dim3 block(WARPS * 32);
    shift_bilinear_kernel<<<grid, block>>>(images, dxdy, out);
}

// round 9
// speedup vs baseline: 1.0734x; 1.0700x over previous
#include <cuda_runtime.h>
#include <cuda_bf16.h>

#define IMG_H 512
#define IMG_W 512
#define N_IMG 256
#define WCHUNK 16                 // rows per warp
#define WARPS  4                  // warps per CTA
#define ROWS_PER_CTA (WCHUNK * WARPS)
#define W4 (IMG_W / 4)            // 128 float4 per row

__device__ __forceinline__ int mirror_idx(int idx, int n) {
    const int p = 2 * (n - 1);
    int i = abs(idx) % p;
    return (i >= n) ? (p - i) : i;
}

// Warp-autonomous: each warp owns a 16-row strip + private smem row buffer.
// grid = 2048 CTAs (measured best residency/BW). Per row: 4 prefetched
// LDG.128/thread (MLP=4), vertical blend in regs, STS, __syncwarp,
// horizontal pass via conflict-free LDS.128, default STG.128.
// Row reuse: rA(y) == rB(y-1) exactly -> 1 global row read per output row.
// Row loop unrolled x2 so the rA/rB/rC rotation becomes register renaming.
__global__ __launch_bounds__(128, 8)
void shift_bilinear_kernel(const float* __restrict__ images,
                           const float* __restrict__ dxdy,
                           float* __restrict__ out) {
    __shared__ float4 sb[WARPS][2][W4];

    const int t = threadIdx.x & 31;
    const int w = threadIdx.x >> 5;
    const int b = blockIdx.y;
    const int y0 = blockIdx.x * ROWS_PER_CTA + w * WCHUNK;

    const float dy = __ldg(&dxdy[2 * b + 0]);
    const float dx = __ldg(&dxdy[2 * b + 1]);

    // per-image constants: floor(y - dy) = y + floor(-dy)
    const float syf = floorf(-dy);
    const float sxf = floorf(-dx);
    const float fy  = (-dy) - syf;
    const float fx  = (-dx) - sxf;
    const float wy0 = 1.0f - fy;
    const float wx0 = 1.0f - fx;
    const int   sy  = (int)syf;
    const int   sx  = (int)sxf;
    const int   kk  = sx >> 2;     // uniform float4-index shift
    const int   sel = sx & 3;      // uniform sub-word select

    const float4* imgv = (const float4*)(images + (size_t)b * IMG_H * IMG_W);
    float4*       outv = (float4*)(out + (size_t)b * IMG_H * IMG_W);

    // preload rA (src row for y0) and rB (next), lane t holds chunks c*32+t
    float4 rA[4], rB[4], rC[4];
    {
        const float4* ra = imgv + (size_t)mirror_idx(y0 + sy,     IMG_H) * W4;
        const float4* rb = imgv + (size_t)mirror_idx(y0 + sy + 1, IMG_H) * W4;
#pragma unroll
        for (int c = 0; c < 4; c++) rA[c] = ra[c * 32 + t];
#pragma unroll
        for (int c = 0; c < 4; c++) rB[c] = rb[c * 32 + t];
    }

#pragma unroll 2
    for (int i = 0; i < WCHUNK; ++i) {
        const int y = y0 + i;

        // prefetch next source row (consumed next iteration) — 4 back-to-back LDG.128
        if (i + 1 < WCHUNK) {
            const float4* rc = imgv + (size_t)mirror_idx(y + sy + 2, IMG_H) * W4;
#pragma unroll
            for (int c = 0; c < 4; c++) rC[c] = rc[c * 32 + t];
        }

        // vertical blend -> private smem buffer (double buffered)
        float4* S = sb[w][i & 1];
#pragma unroll
        for (int c = 0; c < 4; c++) {
            float4 br;
            br.x = wy0 * rA[c].x + fy * rB[c].x;
            br.y = wy0 * rA[c].y + fy * rB[c].y;
            br.z = wy0 * rA[c].z + fy * rB[c].z;
            br.w = wy0 * rA[c].w + fy * rB[c].w;
            S[c * 32 + t] = br;
        }
        __syncwarp();   // STS -> LDS visibility within the warp

        // horizontal pass: output float4 j = c*32+t needs blended float4s j+kk, j+kk+1
        float4* orow = outv + (size_t)y * W4;
#pragma unroll
        for (int c = 0; c < 4; c++) {
            const int j  = c * 32 + t;
            const int q0 = j + kk;
            float4 res;
            if (q0 >= 0 && q0 <= (W4 - 2)) {
                const float4 A = S[q0];
                const float4 B = S[q0 + 1];
                float b0, b1, b2, b3, b4;
                switch (sel) {  // uniform across warp
                    case 0:  b0 = A.x; b1 = A.y; b2 = A.z; b3 = A.w; b4 = B.x; break;
                    case 1:  b0 = A.y; b1 = A.z; b2 = A.w; b3 = B.x; b4 = B.y; break;
                    case 2:  b0 = A.z; b1 = A.w; b2 = B.x; b3 = B.y; b4 = B.z; break;
                    default: b0 = A.w; b1 = B.x; b2 = B.y; b3 = B.z; b4 = B.w; break;
                }
                res.x = wx0 * b0 + fx * b1;
                res.y = wx0 * b1 + fx * b2;
                res.z = wx0 * b2 + fx * b3;
                res.w = wx0 * b3 + fx * b4;
            } else {
                const float* sf = (const float*)S;
                float r[4];
#pragma unroll
                for (int jj = 0; jj < 4; jj++) {
                    const int x0  = 4 * j + sx + jj;
                    const int xm0 = mirror_idx(x0,     IMG_W);
                    const int xm1 = mirror_idx(x0 + 1, IMG_W);
                    r[jj] = wx0 * sf[xm0] + fx * sf[xm1];
                }
                res.x = r[0]; res.y = r[1]; res.z = r[2]; res.w = r[3];
            }
            orow[j] = res;   // default store policy (evict-first regressed)
        }

#pragma unroll
        for (int c = 0; c < 4; c++) { rA[c] = rB[c]; rB[c] = rC[c]; }
    }
}

extern "C" void kernel_launch(void* const* d_in, const int* in_sizes, int n_in,
                              void* d_out, int out_size) {
    const float* images = (const float*)d_in[0];  // (256, 512, 512, 1) f32
    const float* dxdy   = (const float*)d_in[1];  // (256, 2) f32
    float* out = (float*)d_out;                   // (256, 512, 512) f32

    dim3 grid(IMG_H / ROWS_PER_CTA, N_IMG);       // (8, 256) = 2048 CTAs
    dim3 block(WARPS * 32);
    shift_bilinear_kernel<<<grid, block>>>(images, dxdy, out);
}

// round 11
// speedup vs baseline: 1.1157x; 1.0394x over previous
#include <cuda_runtime.h>
#include <cuda_bf16.h>
#include <cstdint>

#define IMG_H 512
#define IMG_W 512
#define N_IMG 256
#define WCHUNK 16                 // rows per warp
#define WARPS  4                  // warps per CTA
#define ROWS_PER_CTA (WCHUNK * WARPS)
#define W4 (IMG_W / 4)            // 128 float4 per row
#define DEPTH 4                   // smem ring slots per warp

__device__ __forceinline__ int mirror_idx(int idx, int n) {
    const int p = 2 * (n - 1);
    int i = abs(idx) % p;
    return (i >= n) ? (p - i) : i;
}

__device__ __forceinline__ void cp_async16(float4* smem_dst, const float4* gsrc) {
    unsigned int s = (unsigned int)__cvta_generic_to_shared(smem_dst);
    asm volatile("cp.async.cg.shared.global [%0], [%1], 16;\n" :: "r"(s), "l"(gsrc));
}
#define CP_COMMIT() asm volatile("cp.async.commit_group;\n" ::: "memory")
#define CP_WAIT2()  asm volatile("cp.async.wait_group 2;\n" ::: "memory")

// lane t copies chunks c*32+t of one 2KB row into a ring slot (RF-bypass)
__device__ __forceinline__ void fill_row(float4* slot, const float4* grow, int t) {
#pragma unroll
    for (int c = 0; c < 4; c++)
        cp_async16(&slot[c * 32 + t], &grow[c * 32 + t]);
}

// pick 5 consecutive floats starting at sel from two adjacent float4s
__device__ __forceinline__ void sel5(const float4 A, const float4 B, const int sel,
                                     float& v0, float& v1, float& v2, float& v3, float& v4) {
    switch (sel) {
        case 0:  v0 = A.x; v1 = A.y; v2 = A.z; v3 = A.w; v4 = B.x; break;
        case 1:  v0 = A.y; v1 = A.z; v2 = A.w; v3 = B.x; v4 = B.y; break;
        case 2:  v0 = A.z; v1 = A.w; v2 = B.x; v3 = B.y; v4 = B.z; break;
        default: v0 = A.w; v1 = B.x; v2 = B.y; v3 = B.z; v4 = B.w; break;
    }
}

// Warp-autonomous strips. Raw source rows stream through a warp-private
// 4-slot cp.async ring (prefetch distance 2 -> ~2 rows of DRAM latency cover,
// zero register payload). Vertical+horizontal bilinear fused at consume time
// from the two raw rows via conflict-free LDS.128.
__global__ __launch_bounds__(128, 7)
void shift_bilinear_kernel(const float* __restrict__ images,
                           const float* __restrict__ dxdy,
                           float* __restrict__ out) {
    __shared__ float4 ring[WARPS][DEPTH][W4];   // 32 KB

    const int t = threadIdx.x & 31;
    const int w = threadIdx.x >> 5;
    const int b = blockIdx.y;
    const int y0 = blockIdx.x * ROWS_PER_CTA + w * WCHUNK;

    const float dy = __ldg(&dxdy[2 * b + 0]);
    const float dx = __ldg(&dxdy[2 * b + 1]);

    // per-image constants: floor(y - dy) = y + floor(-dy)
    const float syf = floorf(-dy);
    const float sxf = floorf(-dx);
    const float fy  = (-dy) - syf;
    const float fx  = (-dx) - sxf;
    const float wy0 = 1.0f - fy;
    const float wx0 = 1.0f - fx;
    const int   sy  = (int)syf;
    const int   sx  = (int)sxf;
    const int   kk  = sx >> 2;     // uniform float4-index shift
    const int   sel = sx & 3;      // uniform sub-word select

    const float4* imgv = (const float4*)(images + (size_t)b * IMG_H * IMG_W);
    float4*       outv = (float4*)(out + (size_t)b * IMG_H * IMG_W);
    float4* const R = &ring[w][0][0];

    // prologue: fills f = 0,1,2 (source rows y0+sy+f), one commit group each
#pragma unroll
    for (int f = 0; f < 3; f++) {
        fill_row(R + (size_t)f * W4,
                 imgv + (size_t)mirror_idx(y0 + sy + f, IMG_H) * W4, t);
        CP_COMMIT();
    }

#pragma unroll 4
    for (int i = 0; i < WCHUNK; ++i) {
        // issue fill f = i+3 (consumed at iterations i+2 / i+3)
        const int f = i + 3;
        if (f <= WCHUNK) {
            fill_row(R + (size_t)(f & (DEPTH - 1)) * W4,
                     imgv + (size_t)mirror_idx(y0 + sy + f, IMG_H) * W4, t);
        }
        CP_COMMIT();            // group even if empty: keeps wait accounting uniform
        CP_WAIT2();             // fills up through f = i+1 complete
        __syncwarp();           // cross-lane visibility of completed fills

        const float4* RA = R + (size_t)(i & (DEPTH - 1)) * W4;        // row y+sy
        const float4* RB = R + (size_t)((i + 1) & (DEPTH - 1)) * W4;  // row y+sy+1

        float4* orow = outv + (size_t)(y0 + i) * W4;
#pragma unroll
        for (int c = 0; c < 4; c++) {
            const int j  = c * 32 + t;
            const int q0 = j + kk;
            float4 res;
            if (q0 >= 0 && q0 <= (W4 - 2)) {
                const float4 A0 = RA[q0], A1 = RA[q0 + 1];
                const float4 B0 = RB[q0], B1 = RB[q0 + 1];
                float a0, a1, a2, a3, a4, b0, b1, b2, b3, b4;
                sel5(A0, A1, sel, a0, a1, a2, a3, a4);
                sel5(B0, B1, sel, b0, b1, b2, b3, b4);
                res.x = wy0 * (wx0 * a0 + fx * a1) + fy * (wx0 * b0 + fx * b1);
                res.y = wy0 * (wx0 * a1 + fx * a2) + fy * (wx0 * b1 + fx * b2);
                res.z = wy0 * (wx0 * a2 + fx * a3) + fy * (wx0 * b2 + fx * b3);
                res.w = wy0 * (wx0 * a3 + fx * a4) + fy * (wx0 * b3 + fx * b4);
            } else {
                const float* ra = (const float*)RA;
                const float* rb = (const float*)RB;
                float r[4];
#pragma unroll
                for (int jj = 0; jj < 4; jj++) {
                    const int x0  = 4 * j + sx + jj;
                    const int xm0 = mirror_idx(x0,     IMG_W);
                    const int xm1 = mirror_idx(x0 + 1, IMG_W);
                    r[jj] = wy0 * (wx0 * ra[xm0] + fx * ra[xm1])
                          + fy  * (wx0 * rb[xm0] + fx * rb[xm1]);
                }
                res.x = r[0]; res.y = r[1]; res.z = r[2]; res.w = r[3];
            }
            orow[j] = res;
        }
        __syncwarp();   // all lanes done reading slot i%4 before fill f=i+4 overwrites it
    }
}

extern "C" void kernel_launch(void* const* d_in, const int* in_sizes, int n_in,
                              void* d_out, int out_size) {
    const float* images = (const float*)d_in[0];  // (256, 512, 512, 1) f32
    const float* dxdy   = (const float*)d_in[1];  // (256, 2) f32
    float* out = (float*)d_out;                   // (256, 512, 512) f32

    dim3 grid(IMG_H / ROWS_PER_CTA, N_IMG);       // (8, 256) = 2048 CTAs
    dim3 block(WARPS * 32);
    shift_bilinear_kernel<<<grid, block>>>(images, dxdy, out);
}